// round 2
// baseline (speedup 1.0000x reference)
#include <cuda_runtime.h>
#include <cuda_bf16.h>

// CenterLoss: loss = sum_i clamp(||pred_i - centers[target_i]||^2, 1e-12, 1e12)
//                    + BATCH*(NUM_CLASSES-1)*1e-12
//
// Shapes: pred [16384, 1024] f32, centers [10000, 1024] f32,
//         target [16384] (int32 on device — jax x64 is disabled, so the
//         requested int64 materializes as int32).
// Output: scalar f32.

#define BATCH       16384
#define NUM_CLASSES 10000
#define FEAT_DIM    1024

// Per-row clamped distances (scratch; device globals allowed, cudaMalloc is not).
__device__ float g_row_dist[BATCH];

// ---------------------------------------------------------------------------
// Kernel 1: one CTA per batch row. 256 threads * float4 = 1024 floats.
// ---------------------------------------------------------------------------
__global__ __launch_bounds__(256, 8)
void center_loss_rows(const float* __restrict__ pred,
                      const float* __restrict__ centers,
                      const int* __restrict__ target)
{
    const int row = blockIdx.x;
    const int tid = threadIdx.x;

    int cls = target[row];  // broadcast load (same addr all threads -> 1 line)
    // Defensive clamp: never fault even if the dtype assumption is off.
    cls = min(max(cls, 0), NUM_CLASSES - 1);

    const float4* p4 = reinterpret_cast<const float4*>(pred    + (size_t)row * FEAT_DIM);
    const float4* c4 = reinterpret_cast<const float4*>(centers + (size_t)cls * FEAT_DIM);

    float4 p = __ldg(&p4[tid]);
    float4 c = __ldg(&c4[tid]);

    float dx = p.x - c.x;
    float dy = p.y - c.y;
    float dz = p.z - c.z;
    float dw = p.w - c.w;
    float s = dx * dx + dy * dy + dz * dz + dw * dw;

    // warp reduce
    #pragma unroll
    for (int off = 16; off > 0; off >>= 1)
        s += __shfl_xor_sync(0xFFFFFFFFu, s, off);

    __shared__ float warp_sum[8];
    const int lane = tid & 31;
    const int wid  = tid >> 5;
    if (lane == 0) warp_sum[wid] = s;
    __syncthreads();

    if (wid == 0) {
        float v = (lane < 8) ? warp_sum[lane] : 0.0f;
        #pragma unroll
        for (int off = 4; off > 0; off >>= 1)
            v += __shfl_xor_sync(0xFFFFFFFFu, v, off);
        if (lane == 0) {
            // clamp(dist, 1e-12, 1e12)
            v = fminf(fmaxf(v, 1e-12f), 1e12f);
            g_row_dist[row] = v;
        }
    }
}

// ---------------------------------------------------------------------------
// Kernel 2: single-CTA deterministic reduction of 16384 partials.
// ---------------------------------------------------------------------------
__global__ __launch_bounds__(1024, 1)
void center_loss_reduce(float* __restrict__ out)
{
    const int tid = threadIdx.x;

    float s = 0.0f;
    #pragma unroll
    for (int i = 0; i < BATCH / 1024; ++i)  // 16 per thread, fixed order
        s += g_row_dist[tid + i * 1024];

    // warp reduce
    #pragma unroll
    for (int off = 16; off > 0; off >>= 1)
        s += __shfl_xor_sync(0xFFFFFFFFu, s, off);

    __shared__ float warp_sum[32];
    const int lane = tid & 31;
    const int wid  = tid >> 5;
    if (lane == 0) warp_sum[wid] = s;
    __syncthreads();

    if (wid == 0) {
        float v = warp_sum[lane];
        #pragma unroll
        for (int off = 16; off > 0; off >>= 1)
            v += __shfl_xor_sync(0xFFFFFFFFu, v, off);
        if (lane == 0) {
            const float masked_const =
                (float)((double)BATCH * (double)(NUM_CLASSES - 1) * 1e-12);
            out[0] = v + masked_const;
        }
    }
}

// ---------------------------------------------------------------------------
extern "C" void kernel_launch(void* const* d_in, const int* in_sizes, int n_in,
                              void* d_out, int out_size)
{
    const float* pred    = (const float*)d_in[0];
    const float* centers = (const float*)d_in[1];
    const int*   target  = (const int*)d_in[2];
    float*       out     = (float*)d_out;

    center_loss_rows<<<BATCH, 256>>>(pred, centers, target);
    center_loss_reduce<<<1, 1024>>>(out);
}

// round 3
// speedup vs baseline: 1.9678x; 1.9678x over previous
#include <cuda_runtime.h>
#include <cuda_bf16.h>

// CenterLoss: loss = sum_i clamp(||pred_i - centers[target_i]||^2, 1e-12, 1e12)
//                    + BATCH*(NUM_CLASSES-1)*1e-12
//
// pred [16384,1024] f32, centers [10000,1024] f32, target [16384] i32.
// Output: scalar f32. Single fused kernel, deterministic reduction.

#define BATCH       16384
#define NUM_CLASSES 10000
#define FEAT_DIM    1024

#define NWARPS      8
#define NTHREADS    (NWARPS * 32)
#define GRID        (BATCH / NWARPS)   // 2048 CTAs, one row per warp

__device__ float g_partial[GRID];
__device__ int   g_ticket = 0;   // self-resetting, starts 0 at module load

__global__ __launch_bounds__(NTHREADS, 8)
void center_loss_fused(const float* __restrict__ pred,
                       const float* __restrict__ centers,
                       const int* __restrict__ target,
                       float* __restrict__ out)
{
    const int tid  = threadIdx.x;
    const int lane = tid & 31;
    const int wid  = tid >> 5;
    const int row  = blockIdx.x * NWARPS + wid;   // one row per warp

    int cls = target[row];
    cls = min(max(cls, 0), NUM_CLASSES - 1);      // never fault

    const float4* p4 = reinterpret_cast<const float4*>(pred    + (size_t)row * FEAT_DIM);
    const float4* c4 = reinterpret_cast<const float4*>(centers + (size_t)cls * FEAT_DIM);

    // 1024 floats / 32 lanes = 8 float4 per lane per operand.
    // Front-batch all 16 loads for maximum MLP.
    float4 p[8], c[8];
    #pragma unroll
    for (int i = 0; i < 8; ++i) p[i] = __ldg(&p4[lane + i * 32]);
    #pragma unroll
    for (int i = 0; i < 8; ++i) c[i] = __ldg(&c4[lane + i * 32]);

    float s = 0.0f;
    #pragma unroll
    for (int i = 0; i < 8; ++i) {
        float dx = p[i].x - c[i].x;
        float dy = p[i].y - c[i].y;
        float dz = p[i].z - c[i].z;
        float dw = p[i].w - c[i].w;
        s = fmaf(dx, dx, s);
        s = fmaf(dy, dy, s);
        s = fmaf(dz, dz, s);
        s = fmaf(dw, dw, s);
    }

    // warp reduce (full xor -> all lanes hold row sum)
    #pragma unroll
    for (int off = 16; off > 0; off >>= 1)
        s += __shfl_xor_sync(0xFFFFFFFFu, s, off);

    // clamp per row
    s = fminf(fmaxf(s, 1e-12f), 1e12f);

    // combine the 8 warp-row sums of this CTA
    __shared__ float warp_sum[NWARPS];
    if (lane == 0) warp_sum[wid] = s;
    __syncthreads();

    __shared__ bool is_last;
    if (tid == 0) {
        float blocksum = 0.0f;
        #pragma unroll
        for (int i = 0; i < NWARPS; ++i) blocksum += warp_sum[i];
        g_partial[blockIdx.x] = blocksum;
        __threadfence();
        int t = atomicAdd(&g_ticket, 1);
        is_last = (t == GRID - 1);
    }
    __syncthreads();

    // Last CTA: deterministic fixed-order reduction of all partials.
    if (is_last) {
        __threadfence();  // acquire: see all g_partial writes
        float v = 0.0f;
        #pragma unroll
        for (int i = 0; i < GRID / NTHREADS; ++i)   // 8 per thread, fixed order
            v += g_partial[tid + i * NTHREADS];

        #pragma unroll
        for (int off = 16; off > 0; off >>= 1)
            v += __shfl_xor_sync(0xFFFFFFFFu, v, off);

        __shared__ float red[NWARPS];
        if (lane == 0) red[wid] = v;
        __syncthreads();

        if (wid == 0) {
            float r = (lane < NWARPS) ? red[lane] : 0.0f;
            #pragma unroll
            for (int off = 4; off > 0; off >>= 1)
                r += __shfl_xor_sync(0xFFFFFFFFu, r, off);
            if (lane == 0) {
                const float masked_const =
                    (float)((double)BATCH * (double)(NUM_CLASSES - 1) * 1e-12);
                out[0] = r + masked_const;
                g_ticket = 0;   // reset for next graph replay (deterministic)
            }
        }
    }
}

extern "C" void kernel_launch(void* const* d_in, const int* in_sizes, int n_in,
                              void* d_out, int out_size)
{
    const float* pred    = (const float*)d_in[0];
    const float* centers = (const float*)d_in[1];
    const int*   target  = (const int*)d_in[2];
    float*       out     = (float*)d_out;

    center_loss_fused<<<GRID, NTHREADS>>>(pred, centers, target, out);
}